// round 16
// baseline (speedup 1.0000x reference)
#include <cuda_runtime.h>
#include <cuda_bf16.h>
#include <math.h>

// Problem constants
#define N_BATCH 4
#define CI 256
#define CO 288          // GROUP(32) * K*K(9)
#define HH 128
#define WW 128
#define OH 126
#define OW 126
#define NPIX (OH*OW)    // 15876
#define GROUPS 32
#define EPSV 1e-5f

// ---------------- scratch (device globals; no allocs allowed) ----------------
__device__ float g_sigma[(size_t)N_BATCH * CO * NPIX];   // conv out -> softmax (in place)  ~73MB
__device__ float g_tmp  [(size_t)N_BATCH * CI * NPIX];   // aggregated (pre-upsample)       ~65MB
__device__ float g_mean[CO];
__device__ float g_rstd[CO];

// ---------------- Kernel 1: direct conv, fp32, register tiled ----------------
// Block tile: 96 cout x (8 rows x 32 cols) pixels. Thread tile: 8 cout x 8 rows.
// blockDim = (32, 12) = 384 threads. Grid: (64 pixel tiles, 3 co tiles, 4 batch)
#define CO_TILE 96
#define CIB 8

__global__ __launch_bounds__(384) void conv_kernel(const float* __restrict__ x,
                                                   const float* __restrict__ w)
{
    __shared__ float x_s[CIB][10][34];       // 10,880 B
    __shared__ float w_s[CIB * 9][100];      // 28,800 B (pad 96->100: aligned f4, low STS conflicts)

    const int tx  = threadIdx.x;             // 0..31  (pixel column)
    const int ty  = threadIdx.y;             // 0..11  (cout group of 8)
    const int tid = ty * 32 + tx;

    const int tile = blockIdx.x;             // 0..63
    const int x0 = (tile & 3) * 32;
    const int y0 = (tile >> 2) * 8;
    const int co0 = blockIdx.y * CO_TILE;
    const int n  = blockIdx.z;

    const float* xb = x + (size_t)n * CI * HH * WW;

    float acc[8][8];
#pragma unroll
    for (int a = 0; a < 8; ++a)
#pragma unroll
        for (int b = 0; b < 8; ++b) acc[a][b] = 0.0f;

    for (int cib = 0; cib < CI / CIB; ++cib) {
        __syncthreads();
        // load input tile: CIB x 10 x 34
        for (int idx = tid; idx < CIB * 10 * 34; idx += 384) {
            int ci  = idx / 340;
            int rem = idx - ci * 340;
            int r   = rem / 34;
            int c   = rem - r * 34;
            int gy = y0 + r, gx = x0 + c;
            float v = 0.0f;
            if (gy < HH && gx < WW)
                v = xb[((size_t)(cib * CIB + ci) * HH + gy) * WW + gx];
            x_s[ci][r][c] = v;
        }
        // load weight tile: 96 cout x (CIB*9) contiguous floats per cout
        for (int idx = tid; idx < CO_TILE * (CIB * 9); idx += 384) {
            int co = idx / 72;
            int r  = idx - co * 72;              // ci_off*9 + k
            float v = w[(size_t)(co0 + co) * (CI * 9) + (size_t)cib * (CIB * 9) + r];
            w_s[r][co] = v;
        }
        __syncthreads();

#pragma unroll 2
        for (int i = 0; i < CIB; ++i) {
#pragma unroll
            for (int kh = 0; kh < 3; ++kh) {
#pragma unroll
                for (int kw = 0; kw < 3; ++kw) {
                    const float* wrow = &w_s[i * 9 + kh * 3 + kw][0];
                    float4 wa = *(const float4*)(wrow + ty * 8);
                    float4 wb = *(const float4*)(wrow + ty * 8 + 4);
                    float wr[8] = {wa.x, wa.y, wa.z, wa.w, wb.x, wb.y, wb.z, wb.w};
                    float xv[8];
#pragma unroll
                    for (int r = 0; r < 8; ++r) xv[r] = x_s[i][r + kh][tx + kw];
#pragma unroll
                    for (int cr = 0; cr < 8; ++cr)
#pragma unroll
                        for (int r = 0; r < 8; ++r)
                            acc[cr][r] = fmaf(wr[cr], xv[r], acc[cr][r]);
                }
            }
        }
    }

    const int gx = x0 + tx;
    if (gx < OW) {
#pragma unroll
        for (int cr = 0; cr < 8; ++cr) {
            int co = co0 + ty * 8 + cr;
            float* dst = g_sigma + (size_t)(n * CO + co) * NPIX;
#pragma unroll
            for (int r = 0; r < 8; ++r) {
                int gy = y0 + r;
                if (gy < OH) dst[(size_t)gy * OW + gx] = acc[cr][r];
            }
        }
    }
}

// ---------------- Kernel 2: per-channel mean / rstd ----------------
__global__ __launch_bounds__(256) void stats_kernel()
{
    const int co  = blockIdx.x;
    const int tid = threadIdx.x;
    float s = 0.0f, s2 = 0.0f;
    for (int n = 0; n < N_BATCH; ++n) {
        const float* p = g_sigma + (size_t)(n * CO + co) * NPIX;
        for (int i = tid; i < NPIX; i += 256) {
            float v = p[i];
            s += v;
            s2 = fmaf(v, v, s2);
        }
    }
    // warp reduce
#pragma unroll
    for (int off = 16; off > 0; off >>= 1) {
        s  += __shfl_down_sync(0xffffffffu, s,  off);
        s2 += __shfl_down_sync(0xffffffffu, s2, off);
    }
    __shared__ float ss[8], ss2[8];
    int lane = tid & 31, wid = tid >> 5;
    if (lane == 0) { ss[wid] = s; ss2[wid] = s2; }
    __syncthreads();
    if (tid < 8) {
        s = ss[tid]; s2 = ss2[tid];
#pragma unroll
        for (int off = 4; off > 0; off >>= 1) {
            s  += __shfl_down_sync(0x000000ffu, s,  off);
            s2 += __shfl_down_sync(0x000000ffu, s2, off);
        }
        if (tid == 0) {
            const float inv = 1.0f / (float)(N_BATCH * NPIX);
            float mean = s * inv;
            float var  = s2 * inv - mean * mean;
            g_mean[co] = mean;
            g_rstd[co] = rsqrtf(var + EPSV);
        }
    }
}

// ---------------- Kernel 3: BN affine + softmax over 288 channels (in place) ----------------
__global__ __launch_bounds__(256) void bn_softmax_kernel(const float* __restrict__ gamma,
                                                         const float* __restrict__ beta)
{
    __shared__ float a_s[CO], b_s[CO];
    for (int c = threadIdx.x; c < CO; c += 256) {
        float r = g_rstd[c], g = gamma[c], m = g_mean[c];
        a_s[c] = r * g;
        b_s[c] = beta[c] - m * r * g;
    }
    __syncthreads();

    int p = blockIdx.x * 256 + threadIdx.x;
    if (p >= N_BATCH * NPIX) return;
    int n   = p / NPIX;
    int pix = p - n * NPIX;
    float* base = g_sigma + (size_t)n * CO * NPIX + pix;

    // online (branch-free) softmax: pass 1 computes max & scaled sum
    float m = -1e30f, s = 0.0f;
    for (int c = 0; c < CO; ++c) {
        float t  = fmaf(base[(size_t)c * NPIX], a_s[c], b_s[c]);
        float mn = fmaxf(m, t);
        s = s * __expf(m - mn) + __expf(t - mn);
        m = mn;
    }
    float inv = 1.0f / s;
    for (int c = 0; c < CO; ++c) {
        float t = fmaf(base[(size_t)c * NPIX], a_s[c], b_s[c]);
        base[(size_t)c * NPIX] = __expf(t - m) * inv;
    }
}

// ---------------- Kernel 4: per-group weighted 3x3 patch aggregation ----------------
__global__ __launch_bounds__(256) void aggregate_kernel(const float* __restrict__ x)
{
    size_t idx = (size_t)blockIdx.x * 256 + threadIdx.x;
    if (idx >= (size_t)N_BATCH * CI * NPIX) return;
    int pix = (int)(idx % NPIX);
    int nc  = (int)(idx / NPIX);
    int c   = nc & 255;
    int n   = nc >> 8;
    int y   = pix / OW;
    int xx  = pix - y * OW;

    const float* xb = x + ((size_t)(n * CI + c) * HH + y) * WW + xx;
    const float* sb = g_sigma + (size_t)(n * CO + (c >> 3) * 9) * NPIX + pix;

    float acc = 0.0f;
#pragma unroll
    for (int kh = 0; kh < 3; ++kh)
#pragma unroll
        for (int kw = 0; kw < 3; ++kw)
            acc = fmaf(xb[kh * WW + kw], sb[(size_t)(kh * 3 + kw) * NPIX], acc);

    g_tmp[idx] = acc;
}

// ---------------- Kernel 5: bilinear upsample 126 -> 128 (align_corners) ----------------
__global__ __launch_bounds__(256) void upsample_kernel(float* __restrict__ out)
{
    size_t idx = (size_t)blockIdx.x * 256 + threadIdx.x;
    if (idx >= (size_t)N_BATCH * CI * HH * WW) return;
    int X  = (int)(idx & 127);
    int Y  = (int)((idx >> 7) & 127);
    int nc = (int)(idx >> 14);

    const float step = 125.0f / 127.0f;   // (h-1)/(H-1), align_corners
    float fy = (float)Y * step;
    float fx = (float)X * step;
    int y0 = (int)fy, x0 = (int)fx;
    int y1 = min(y0 + 1, OH - 1);
    int x1 = min(x0 + 1, OW - 1);
    float wy = fy - (float)y0;
    float wx = fx - (float)x0;

    const float* b = g_tmp + (size_t)nc * NPIX;
    float v00 = b[(size_t)y0 * OW + x0];
    float v01 = b[(size_t)y0 * OW + x1];
    float v10 = b[(size_t)y1 * OW + x0];
    float v11 = b[(size_t)y1 * OW + x1];

    float top = v00 + (v01 - v00) * wx;
    float bot = v10 + (v11 - v10) * wx;
    out[idx] = top + (bot - top) * wy;
}

// ---------------- launch ----------------
extern "C" void kernel_launch(void* const* d_in, const int* in_sizes, int n_in,
                              void* d_out, int out_size)
{
    const float* x     = (const float*)d_in[0];   // (4,256,128,128)
    const float* cw    = (const float*)d_in[1];   // (288,256,3,3)
    const float* gamma = (const float*)d_in[2];   // (288,)
    const float* beta  = (const float*)d_in[3];   // (288,)
    float* out = (float*)d_out;                   // (4,256,128,128)

    // 1) conv -> g_sigma
    {
        dim3 grid(64, CO / CO_TILE, N_BATCH);
        dim3 block(32, 12);
        conv_kernel<<<grid, block>>>(x, cw);
    }
    // 2) per-channel stats
    stats_kernel<<<CO, 256>>>();
    // 3) BN + softmax in place
    {
        int total = N_BATCH * NPIX;
        bn_softmax_kernel<<<(total + 255) / 256, 256>>>(gamma, beta);
    }
    // 4) weighted patch aggregation -> g_tmp
    {
        size_t total = (size_t)N_BATCH * CI * NPIX;
        aggregate_kernel<<<(unsigned)((total + 255) / 256), 256>>>(x);
    }
    // 5) bilinear upsample -> out
    {
        size_t total = (size_t)N_BATCH * CI * HH * WW;
        upsample_kernel<<<(unsigned)((total + 255) / 256), 256>>>(out);
    }
}

// round 17
// speedup vs baseline: 1.0000x; 1.0000x over previous
#include <cuda_runtime.h>
#include <cuda_bf16.h>
#include <math.h>

// Problem constants
#define N_BATCH 4
#define CI 256
#define CO 288          // GROUP(32) * K*K(9)
#define HH 128
#define WW 128
#define OH 126
#define OW 126
#define NPIX (OH*OW)    // 15876
#define GROUPS 32
#define EPSV 1e-5f

// ---------------- scratch (device globals; no allocs allowed) ----------------
__device__ float g_sigma[(size_t)N_BATCH * CO * NPIX];   // conv out -> softmax (in place)  ~73MB
__device__ float g_tmp  [(size_t)N_BATCH * CI * NPIX];   // aggregated (pre-upsample)       ~65MB
__device__ float g_mean[CO];
__device__ float g_rstd[CO];

// ---------------- Kernel 1: direct conv, fp32, register tiled ----------------
// Block tile: 96 cout x (8 rows x 32 cols) pixels. Thread tile: 8 cout x 8 rows.
// blockDim = (32, 12) = 384 threads. Grid: (64 pixel tiles, 3 co tiles, 4 batch)
#define CO_TILE 96
#define CIB 8

__global__ __launch_bounds__(384) void conv_kernel(const float* __restrict__ x,
                                                   const float* __restrict__ w)
{
    __shared__ float x_s[CIB][10][34];       // 10,880 B
    __shared__ float w_s[CIB * 9][100];      // 28,800 B (pad 96->100: aligned f4, low STS conflicts)

    const int tx  = threadIdx.x;             // 0..31  (pixel column)
    const int ty  = threadIdx.y;             // 0..11  (cout group of 8)
    const int tid = ty * 32 + tx;

    const int tile = blockIdx.x;             // 0..63
    const int x0 = (tile & 3) * 32;
    const int y0 = (tile >> 2) * 8;
    const int co0 = blockIdx.y * CO_TILE;
    const int n  = blockIdx.z;

    const float* xb = x + (size_t)n * CI * HH * WW;

    float acc[8][8];
#pragma unroll
    for (int a = 0; a < 8; ++a)
#pragma unroll
        for (int b = 0; b < 8; ++b) acc[a][b] = 0.0f;

    for (int cib = 0; cib < CI / CIB; ++cib) {
        __syncthreads();
        // load input tile: CIB x 10 x 34
        for (int idx = tid; idx < CIB * 10 * 34; idx += 384) {
            int ci  = idx / 340;
            int rem = idx - ci * 340;
            int r   = rem / 34;
            int c   = rem - r * 34;
            int gy = y0 + r, gx = x0 + c;
            float v = 0.0f;
            if (gy < HH && gx < WW)
                v = xb[((size_t)(cib * CIB + ci) * HH + gy) * WW + gx];
            x_s[ci][r][c] = v;
        }
        // load weight tile: 96 cout x (CIB*9) contiguous floats per cout
        for (int idx = tid; idx < CO_TILE * (CIB * 9); idx += 384) {
            int co = idx / 72;
            int r  = idx - co * 72;              // ci_off*9 + k
            float v = w[(size_t)(co0 + co) * (CI * 9) + (size_t)cib * (CIB * 9) + r];
            w_s[r][co] = v;
        }
        __syncthreads();

#pragma unroll 2
        for (int i = 0; i < CIB; ++i) {
#pragma unroll
            for (int kh = 0; kh < 3; ++kh) {
#pragma unroll
                for (int kw = 0; kw < 3; ++kw) {
                    const float* wrow = &w_s[i * 9 + kh * 3 + kw][0];
                    float4 wa = *(const float4*)(wrow + ty * 8);
                    float4 wb = *(const float4*)(wrow + ty * 8 + 4);
                    float wr[8] = {wa.x, wa.y, wa.z, wa.w, wb.x, wb.y, wb.z, wb.w};
                    float xv[8];
#pragma unroll
                    for (int r = 0; r < 8; ++r) xv[r] = x_s[i][r + kh][tx + kw];
#pragma unroll
                    for (int cr = 0; cr < 8; ++cr)
#pragma unroll
                        for (int r = 0; r < 8; ++r)
                            acc[cr][r] = fmaf(wr[cr], xv[r], acc[cr][r]);
                }
            }
        }
    }

    const int gx = x0 + tx;
    if (gx < OW) {
#pragma unroll
        for (int cr = 0; cr < 8; ++cr) {
            int co = co0 + ty * 8 + cr;
            float* dst = g_sigma + (size_t)(n * CO + co) * NPIX;
#pragma unroll
            for (int r = 0; r < 8; ++r) {
                int gy = y0 + r;
                if (gy < OH) dst[(size_t)gy * OW + gx] = acc[cr][r];
            }
        }
    }
}

// ---------------- Kernel 2: per-channel mean / rstd ----------------
__global__ __launch_bounds__(256) void stats_kernel()
{
    const int co  = blockIdx.x;
    const int tid = threadIdx.x;
    float s = 0.0f, s2 = 0.0f;
    for (int n = 0; n < N_BATCH; ++n) {
        const float* p = g_sigma + (size_t)(n * CO + co) * NPIX;
        for (int i = tid; i < NPIX; i += 256) {
            float v = p[i];
            s += v;
            s2 = fmaf(v, v, s2);
        }
    }
    // warp reduce
#pragma unroll
    for (int off = 16; off > 0; off >>= 1) {
        s  += __shfl_down_sync(0xffffffffu, s,  off);
        s2 += __shfl_down_sync(0xffffffffu, s2, off);
    }
    __shared__ float ss[8], ss2[8];
    int lane = tid & 31, wid = tid >> 5;
    if (lane == 0) { ss[wid] = s; ss2[wid] = s2; }
    __syncthreads();
    if (tid < 8) {
        s = ss[tid]; s2 = ss2[tid];
#pragma unroll
        for (int off = 4; off > 0; off >>= 1) {
            s  += __shfl_down_sync(0x000000ffu, s,  off);
            s2 += __shfl_down_sync(0x000000ffu, s2, off);
        }
        if (tid == 0) {
            const float inv = 1.0f / (float)(N_BATCH * NPIX);
            float mean = s * inv;
            float var  = s2 * inv - mean * mean;
            g_mean[co] = mean;
            g_rstd[co] = rsqrtf(var + EPSV);
        }
    }
}

// ---------------- Kernel 3: BN affine + softmax over 288 channels (in place) ----------------
__global__ __launch_bounds__(256) void bn_softmax_kernel(const float* __restrict__ gamma,
                                                         const float* __restrict__ beta)
{
    __shared__ float a_s[CO], b_s[CO];
    for (int c = threadIdx.x; c < CO; c += 256) {
        float r = g_rstd[c], g = gamma[c], m = g_mean[c];
        a_s[c] = r * g;
        b_s[c] = beta[c] - m * r * g;
    }
    __syncthreads();

    int p = blockIdx.x * 256 + threadIdx.x;
    if (p >= N_BATCH * NPIX) return;
    int n   = p / NPIX;
    int pix = p - n * NPIX;
    float* base = g_sigma + (size_t)n * CO * NPIX + pix;

    // online (branch-free) softmax: pass 1 computes max & scaled sum
    float m = -1e30f, s = 0.0f;
    for (int c = 0; c < CO; ++c) {
        float t  = fmaf(base[(size_t)c * NPIX], a_s[c], b_s[c]);
        float mn = fmaxf(m, t);
        s = s * __expf(m - mn) + __expf(t - mn);
        m = mn;
    }
    float inv = 1.0f / s;
    for (int c = 0; c < CO; ++c) {
        float t = fmaf(base[(size_t)c * NPIX], a_s[c], b_s[c]);
        base[(size_t)c * NPIX] = __expf(t - m) * inv;
    }
}

// ---------------- Kernel 4: per-group weighted 3x3 patch aggregation ----------------
__global__ __launch_bounds__(256) void aggregate_kernel(const float* __restrict__ x)
{
    size_t idx = (size_t)blockIdx.x * 256 + threadIdx.x;
    if (idx >= (size_t)N_BATCH * CI * NPIX) return;
    int pix = (int)(idx % NPIX);
    int nc  = (int)(idx / NPIX);
    int c   = nc & 255;
    int n   = nc >> 8;
    int y   = pix / OW;
    int xx  = pix - y * OW;

    const float* xb = x + ((size_t)(n * CI + c) * HH + y) * WW + xx;
    const float* sb = g_sigma + (size_t)(n * CO + (c >> 3) * 9) * NPIX + pix;

    float acc = 0.0f;
#pragma unroll
    for (int kh = 0; kh < 3; ++kh)
#pragma unroll
        for (int kw = 0; kw < 3; ++kw)
            acc = fmaf(xb[kh * WW + kw], sb[(size_t)(kh * 3 + kw) * NPIX], acc);

    g_tmp[idx] = acc;
}

// ---------------- Kernel 5: bilinear upsample 126 -> 128 (align_corners) ----------------
__global__ __launch_bounds__(256) void upsample_kernel(float* __restrict__ out)
{
    size_t idx = (size_t)blockIdx.x * 256 + threadIdx.x;
    if (idx >= (size_t)N_BATCH * CI * HH * WW) return;
    int X  = (int)(idx & 127);
    int Y  = (int)((idx >> 7) & 127);
    int nc = (int)(idx >> 14);

    const float step = 125.0f / 127.0f;   // (h-1)/(H-1), align_corners
    float fy = (float)Y * step;
    float fx = (float)X * step;
    int y0 = (int)fy, x0 = (int)fx;
    int y1 = min(y0 + 1, OH - 1);
    int x1 = min(x0 + 1, OW - 1);
    float wy = fy - (float)y0;
    float wx = fx - (float)x0;

    const float* b = g_tmp + (size_t)nc * NPIX;
    float v00 = b[(size_t)y0 * OW + x0];
    float v01 = b[(size_t)y0 * OW + x1];
    float v10 = b[(size_t)y1 * OW + x0];
    float v11 = b[(size_t)y1 * OW + x1];

    float top = v00 + (v01 - v00) * wx;
    float bot = v10 + (v11 - v10) * wx;
    out[idx] = top + (bot - top) * wy;
}

// ---------------- launch ----------------
extern "C" void kernel_launch(void* const* d_in, const int* in_sizes, int n_in,
                              void* d_out, int out_size)
{
    const float* x     = (const float*)d_in[0];   // (4,256,128,128)
    const float* cw    = (const float*)d_in[1];   // (288,256,3,3)
    const float* gamma = (const float*)d_in[2];   // (288,)
    const float* beta  = (const float*)d_in[3];   // (288,)
    float* out = (float*)d_out;                   // (4,256,128,128)

    // 1) conv -> g_sigma
    {
        dim3 grid(64, CO / CO_TILE, N_BATCH);
        dim3 block(32, 12);
        conv_kernel<<<grid, block>>>(x, cw);
    }
    // 2) per-channel stats
    stats_kernel<<<CO, 256>>>();
    // 3) BN + softmax in place
    {
        int total = N_BATCH * NPIX;
        bn_softmax_kernel<<<(total + 255) / 256, 256>>>(gamma, beta);
    }
    // 4) weighted patch aggregation -> g_tmp
    {
        size_t total = (size_t)N_BATCH * CI * NPIX;
        aggregate_kernel<<<(unsigned)((total + 255) / 256), 256>>>(x);
    }
    // 5) bilinear upsample -> out
    {
        size_t total = (size_t)N_BATCH * CI * HH * WW;
        upsample_kernel<<<(unsigned)((total + 255) / 256), 256>>>(out);
    }
}